// round 17
// baseline (speedup 1.0000x reference)
#include <cuda_runtime.h>
#include <cuda_fp16.h>
#include <cstdint>
#include <math.h>

#define B_   8
#define T_   4096
#define C_   384
#define HD   64

// ---------------------------------------------------------------------------
// scratch (__device__ globals)
// g_Q : fp16 [b*T+t][h_phys], h phi2-permuted within 16-groups, pre-scaled by
//       log2(e)/sqrt(384)  (softmax runs in exp2 domain)
// g_K : fp16 [b*T+t][h]  (natural h — ldmatrix does the lane shuffle)
// g_Vt: fp16 [b][h][t]   (natural t)
// g_WT: W fp16, [m*64+col][k], k phi2-permuted within 16-groups
// g_Po: fp16 partial O; g_Pl: fp32 partial l
// ---------------------------------------------------------------------------
__device__ __half g_Q [(size_t)B_ * T_ * HD];
__device__ __half g_K [(size_t)B_ * T_ * HD];
__device__ __half g_Vt[(size_t)B_ * HD * T_];
__device__ __half g_WT[3 * 64 * C_];
__device__ __half g_Po[(size_t)B_ * 32 * 2 * 128 * 64];
__device__ float  g_Pl[(size_t)B_ * 32 * 2 * 128];

__device__ __forceinline__ uint32_t smem_u32(const void* p) {
    uint32_t a;
    asm("{ .reg .u64 t; cvta.to.shared.u64 t, %1; cvt.u32.u64 %0, t; }"
        : "=r"(a) : "l"(p));
    return a;
}
// pack two f32 -> f16x2 (first arg in low half)
__device__ __forceinline__ uint32_t h2pack(float lo, float hi) {
    uint32_t r;
    asm("cvt.rn.f16x2.f32 %0, %1, %2;" : "=r"(r) : "f"(hi), "f"(lo));
    return r;
}
__device__ __forceinline__ float ex2f(float x) {
    float r;
    asm("ex2.approx.f32 %0, %1;" : "=f"(r) : "f"(x));
    return r;
}

// mma m16n8k16 f16 (f32 accum)
#define MMA16(c, a0, a1, a2, a3, b0, b1)                                       \
    asm volatile(                                                              \
        "mma.sync.aligned.m16n8k16.row.col.f32.f16.f16.f32 "                   \
        "{%0,%1,%2,%3}, {%4,%5,%6,%7}, {%8,%9}, {%0,%1,%2,%3};"                \
        : "+f"((c)[0]), "+f"((c)[1]), "+f"((c)[2]), "+f"((c)[3])               \
        : "r"(a0), "r"(a1), "r"(a2), "r"(a3), "r"(b0), "r"(b1))

// ldmatrix x4: 4 8x8 b16 matrices
#define LDSM4(r0, r1, r2, r3, addr)                                            \
    asm volatile(                                                              \
        "ldmatrix.sync.aligned.m8n8.x4.shared.b16 {%0,%1,%2,%3}, [%4];"        \
        : "=r"(r0), "=r"(r1), "=r"(r2), "=r"(r3) : "r"(addr))

#define CP16(dst, src) \
    asm volatile("cp.async.cg.shared.global [%0], [%1], 16;" :: "r"(dst), "l"(src))
#define CP_COMMIT() asm volatile("cp.async.commit_group;" ::: "memory")
#define CP_WAIT0()  asm volatile("cp.async.wait_group 0;"  ::: "memory")

// ---------------------------------------------------------------------------
// Setup: W -> fp16, transposed [m*64+col][k], k phi2-permuted.
// ---------------------------------------------------------------------------
__global__ __launch_bounds__(256) void split_w_kernel(
    const float* __restrict__ Wk,
    const float* __restrict__ Wq,
    const float* __restrict__ Wv)
{
    int idx = blockIdx.x * 256 + threadIdx.x;      // 3*24*64 = 4608
    if (idx >= 3 * 24 * 64) return;
    int m   = idx / (24 * 64);
    int rem = idx % (24 * 64);
    int kg  = rem >> 6;
    int col = rem & 63;
    const float* Wm = (m == 0) ? Wq : (m == 1) ? Wk : Wv;

    __align__(16) __half hp[16];
    #pragma unroll
    for (int u = 0; u < 16; ++u) {
        float w = Wm[(size_t)(kg * 16 + u) * HD + col];
        int q = u >> 1, c = u & 1;
        int up = (q < 4) ? 4 * q + c : 4 * (q - 4) + 2 + c;
        hp[up] = __float2half_rn(w);
    }
    __half* dst = g_WT + (size_t)(m * 64 + col) * C_ + kg * 16;
    *(uint4*)dst       = *(uint4*)hp;
    *(uint4*)(dst + 8) = *(uint4*)(hp + 8);
}

// ---------------------------------------------------------------------------
// Projection: single-pass fp16, m16n8k16, K chunks of 64 (6 iterations).
// smem/buf: x[64 rows x 288B] fp32 | w[192 cols x 160B] f16
// ---------------------------------------------------------------------------
#define PXB   (64 * 288)              // 18432 B
#define PWB   (192 * 160)             // 30720 B
#define PBUFB (PXB + PWB)             // 49152 B
#define SMEM_PROJ (2 * PBUFB)         // 98304 B

__global__ __launch_bounds__(256, 2) void proj_mma_kernel(
    const float* __restrict__ x)
{
    extern __shared__ __align__(16) char psm[];
    const uint32_t sbase = smem_u32(psm);

    const int tid  = threadIdx.x;
    const int wid  = tid >> 5;
    const int lane = tid & 31;
    const int g    = lane >> 2;
    const int t4   = lane & 3;
    const int wr   = (wid & 3) * 16;
    const int wc   = (wid >> 2) * 96;
    const size_t rowbase = (size_t)blockIdx.x * 64;

    auto prefetch = [&](int kb, int buf) {
        #pragma unroll
        for (int it = 0; it < 4; ++it) {
            int idx = tid + it * 256;
            int row = idx >> 4, c16 = idx & 15;
            uint32_t d = sbase + (uint32_t)(buf * PBUFB + row * 288 + c16 * 16);
            CP16(d, x + (rowbase + row) * C_ + kb + c16 * 4);
        }
        #pragma unroll
        for (int it = 0; it < 6; ++it) {
            int idx = tid + it * 256;
            int col = idx >> 3, seg = idx & 7;
            uint32_t d = sbase + (uint32_t)(buf * PBUFB + PXB + col * 160 + seg * 16);
            CP16(d, g_WT + (size_t)col * C_ + kb + seg * 8);
        }
    };

    float c[12][4] = {};

    prefetch(0, 0);
    CP_COMMIT();

    for (int ch = 0; ch < 6; ++ch) {
        const int buf = ch & 1;
        CP_WAIT0();
        __syncthreads();
        if (ch + 1 < 6) { prefetch((ch + 1) * 64, buf ^ 1); CP_COMMIT(); }

        const float* xb = (const float*)(psm + buf * PBUFB);
        const char*  wb = psm + buf * PBUFB + PXB;

        #pragma unroll
        for (int kt2 = 0; kt2 < 4; ++kt2) {
            float2 f0 = *(const float2*)&xb[(wr + g) * 72 + kt2 * 16 + 2 * t4];
            float2 f1 = *(const float2*)&xb[(wr + g) * 72 + kt2 * 16 + 2 * t4 + 8];
            float2 f2 = *(const float2*)&xb[(wr + g + 8) * 72 + kt2 * 16 + 2 * t4];
            float2 f3 = *(const float2*)&xb[(wr + g + 8) * 72 + kt2 * 16 + 2 * t4 + 8];
            uint32_t a0 = h2pack(f0.x, f0.y), a1 = h2pack(f2.x, f2.y);
            uint32_t a2 = h2pack(f1.x, f1.y), a3 = h2pack(f3.x, f3.y);
            #pragma unroll
            for (int nt = 0; nt < 12; ++nt) {
                const int col = wc + nt * 8 + g;
                uint2 bw = *(const uint2*)(wb + col * 160 + kt2 * 32 + 8 * t4);
                MMA16(c[nt], a0, a1, a2, a3, bw.x, bw.y);
            }
        }
        __syncthreads();
    }

    // ---- epilogue ----
    const float scale = 0.07362222433f;   // log2(e)/sqrt(384)
    const int bb = (int)(rowbase >> 12);
    const int t0 = (int)(rowbase & 4095);
    const size_t r0g = rowbase + wr + g;
    const size_t r1g = r0g + 8;
    const int tl0 = t0 + wr + g;
    const int tl1 = tl0 + 8;

    #pragma unroll
    for (int nt = 0; nt < 12; ++nt) {
        const int colb = wc + nt * 8;
        if (colb < 64) {            // Q (scaled): phi2-permuted h pair
            int pc = (colb & ~15) + 4 * t4 + (((colb >> 3) & 1) << 1);
            *(uint32_t*)((__half*)g_Q + r0g * 64 + pc) =
                h2pack(c[nt][0] * scale, c[nt][1] * scale);
            *(uint32_t*)((__half*)g_Q + r1g * 64 + pc) =
                h2pack(c[nt][2] * scale, c[nt][3] * scale);
        } else if (colb < 128) {    // K: natural h
            int pc = (colb - 64) + 2 * t4;
            *(uint32_t*)((__half*)g_K + r0g * 64 + pc) = h2pack(c[nt][0], c[nt][1]);
            *(uint32_t*)((__half*)g_K + r1g * 64 + pc) = h2pack(c[nt][2], c[nt][3]);
        } else {                    // V: transposed, natural t
            int h0 = colb - 128 + 2 * t4;
            g_Vt[((size_t)bb * HD + h0)     * T_ + tl0] = __float2half_rn(c[nt][0]);
            g_Vt[((size_t)bb * HD + h0 + 1) * T_ + tl0] = __float2half_rn(c[nt][1]);
            g_Vt[((size_t)bb * HD + h0)     * T_ + tl1] = __float2half_rn(c[nt][2]);
            g_Vt[((size_t)bb * HD + h0 + 1) * T_ + tl1] = __float2half_rn(c[nt][3]);
        }
    }
}

// ---------------------------------------------------------------------------
// Flash attention (split-K). S and PV fp16 m16n8k16, f32 accum.
// Double-buffered K/V. Fully-masked warp-tiles (diag tile kt=2qt+1, warps 0-3)
// are skipped entirely — they contribute exact zeros.
// ---------------------------------------------------------------------------
#define KVROW_B  144
#define KBUF_B   (64 * KVROW_B)            // 9216 per buf
#define V_BASE   (2 * KBUF_B)              // 18432
#define SMEM_ATTN (4 * KBUF_B)             // 36864

__global__ __launch_bounds__(256, 2) void attn_kernel()
{
    extern __shared__ __align__(16) char smc[];
    const uint32_t sbase = smem_u32(smc);

    const int tid  = threadIdx.x;
    const int wid  = tid >> 5;
    const int lane = tid & 31;
    const int g    = lane >> 2;
    const int t4   = lane & 3;
    const int b    = blockIdx.x;
    const int yy   = blockIdx.y;
    const int qt   = 31 - (yy >> 1);      // biggest first
    const int half = yy & 1;
    const int qbase = qt << 7;
    const int kt0  = half ? (qt + 1) : 0;
    const int kt1  = half ? (2 * qt + 2) : (qt + 1);
    const int r0   = wid * 16 + g;
    const int grow0 = qbase + r0;
    const int grow1 = grow0 + 8;

    const int mat = lane >> 3;
    const uint32_t lds_off =
        (uint32_t)((((mat >> 1) * 8 + (lane & 7)) * KVROW_B) + (mat & 1) * 16);

    // ---- Q A-frags directly from gmem (phi2-permuted fp16) ----
    uint32_t qf[4][4];
    {
        const uint2* q0 = (const uint2*)(g_Q + ((size_t)b * T_ + grow0) * 64);
        const uint2* q1 = (const uint2*)(g_Q + ((size_t)b * T_ + grow1) * 64);
        #pragma unroll
        for (int kt = 0; kt < 4; ++kt) {
            uint2 u0 = q0[4 * kt + t4];
            uint2 u1 = q1[4 * kt + t4];
            qf[kt][0] = u0.x;
            qf[kt][1] = u1.x;
            qf[kt][2] = u0.y;
            qf[kt][3] = u1.y;
        }
    }

    auto prefetch = [&](int kt, int buf) {
        const __half* Kg = g_K + ((size_t)b * T_ + (size_t)kt * 64) * 64;
        #pragma unroll
        for (int it = 0; it < 2; ++it) {
            int idx = tid + it * 256;          // 512 x 16B
            int j = idx >> 3, c16 = idx & 7;
            uint32_t d = sbase + (uint32_t)(buf * KBUF_B + j * KVROW_B + c16 * 16);
            CP16(d, Kg + (size_t)j * 64 + c16 * 8);
        }
        const __half* Vg = g_Vt + ((size_t)b * HD) * T_ + (size_t)kt * 64;
        #pragma unroll
        for (int it = 0; it < 2; ++it) {
            int idx = tid + it * 256;
            int h = idx >> 3, c16 = idx & 7;
            uint32_t d = sbase + (uint32_t)(V_BASE + buf * KBUF_B + h * KVROW_B + c16 * 16);
            CP16(d, Vg + (size_t)h * T_ + c16 * 8);
        }
    };

    float o[8][4] = {};
    float lsum0 = 0.0f, lsum1 = 0.0f;

    prefetch(kt0, 0);
    CP_COMMIT();

    for (int kt = kt0; kt < kt1; ++kt) {
        const int buf = (kt - kt0) & 1;
        CP_WAIT0();
        __syncthreads();
        if (kt + 1 < kt1) { prefetch(kt + 1, buf ^ 1); CP_COMMIT(); }

        // diag tile kt==2qt+1: warps 0-3 (rows qbase..+63 < cols qbase+64..)
        // are FULLY masked -> skip all compute (warp-uniform predicate).
        const bool full_skip = (kt == 2 * qt + 1) && (wid < 4);
        if (full_skip) continue;       // barrier already passed; safe
        // partial mask needed only for: kt==2qt & warps 0-3, kt==2qt+1 & warps 4-7
        const bool part_mask = (kt == 2 * qt && wid < 4) ||
                               (kt == 2 * qt + 1 && wid >= 4);

        // ---- S = Q K^T (fp16, f32 accum); B via ldmatrix ----
        float s[8][4] = {};
        const uint32_t kb_base = sbase + (uint32_t)(buf * KBUF_B) + lds_off;
        #pragma unroll
        for (int k16 = 0; k16 < 4; ++k16) {
            #pragma unroll
            for (int ntp = 0; ntp < 4; ++ntp) {
                uint32_t b0, b1, b2, b3;
                LDSM4(b0, b1, b2, b3,
                      kb_base + (uint32_t)(ntp * 16 * KVROW_B + k16 * 32));
                MMA16(s[2 * ntp],     qf[k16][0], qf[k16][1], qf[k16][2], qf[k16][3], b0, b1);
                MMA16(s[2 * ntp + 1], qf[k16][0], qf[k16][1], qf[k16][2], qf[k16][3], b2, b3);
            }
        }

        // ---- softmax (exp2 domain) -> fp16 A-frags; lsum via HADD2 tree ----
        uint32_t pa[4][4];
        if (!part_mask) {
            #pragma unroll
            for (int n = 0; n < 8; ++n) {
                uint32_t lo = h2pack(s[n][0], s[n][1]);
                uint32_t hi = h2pack(s[n][2], s[n][3]);
                asm("ex2.approx.f16x2 %0, %0;" : "+r"(lo));
                asm("ex2.approx.f16x2 %0, %0;" : "+r"(hi));
                const int kk = n >> 1;
                if ((n & 1) == 0) { pa[kk][0] = lo; pa[kk][1] = hi; }
                else              { pa[kk][2] = lo; pa[kk][3] = hi; }
            }
            __half2 sL = __hadd2(__hadd2(*(__half2*)&pa[0][0], *(__half2*)&pa[0][2]),
                                 __hadd2(*(__half2*)&pa[1][0], *(__half2*)&pa[1][2]));
            sL = __hadd2(sL,
                 __hadd2(__hadd2(*(__half2*)&pa[2][0], *(__half2*)&pa[2][2]),
                         __hadd2(*(__half2*)&pa[3][0], *(__half2*)&pa[3][2])));
            __half2 sH = __hadd2(__hadd2(*(__half2*)&pa[0][1], *(__half2*)&pa[0][3]),
                                 __hadd2(*(__half2*)&pa[1][1], *(__half2*)&pa[1][3]));
            sH = __hadd2(sH,
                 __hadd2(__hadd2(*(__half2*)&pa[2][1], *(__half2*)&pa[2][3]),
                         __hadd2(*(__half2*)&pa[3][1], *(__half2*)&pa[3][3])));
            float2 fL = __half22float2(sL);
            float2 fH = __half22float2(sH);
            lsum0 += fL.x + fL.y;
            lsum1 += fH.x + fH.y;
        } else {
            const int jb = kt << 6;
            #pragma unroll
            for (int n = 0; n < 8; ++n) {
                int c0 = jb + n * 8 + 2 * t4;
                float p0 = ex2f(s[n][0]);
                float p1 = ex2f(s[n][1]);
                float p2 = ex2f(s[n][2]);
                float p3 = ex2f(s[n][3]);
                if (c0     > grow0) p0 = 0.0f;
                if (c0 + 1 > grow0) p1 = 0.0f;
                if (c0     > grow1) p2 = 0.0f;
                if (c0 + 1 > grow1) p3 = 0.0f;
                uint32_t lo = h2pack(p0, p1);
                uint32_t hi = h2pack(p2, p3);
                float2 lof = __half22float2(*(__half2*)&lo);
                float2 hif = __half22float2(*(__half2*)&hi);
                lsum0 += lof.x + lof.y;
                lsum1 += hif.x + hif.y;
                const int kk = n >> 1;
                if ((n & 1) == 0) { pa[kk][0] = lo; pa[kk][1] = hi; }
                else              { pa[kk][2] = lo; pa[kk][3] = hi; }
            }
        }

        // ---- O += P V (fp16); B via ldmatrix ----
        const uint32_t vb_base = sbase + (uint32_t)(V_BASE + buf * KBUF_B) + lds_off;
        #pragma unroll
        for (int kk = 0; kk < 4; ++kk) {
            #pragma unroll
            for (int ntp = 0; ntp < 4; ++ntp) {
                uint32_t b0, b1, b2, b3;
                LDSM4(b0, b1, b2, b3,
                      vb_base + (uint32_t)(ntp * 16 * KVROW_B + kk * 32));
                MMA16(o[2 * ntp],     pa[kk][0], pa[kk][1], pa[kk][2], pa[kk][3], b0, b1);
                MMA16(o[2 * ntp + 1], pa[kk][0], pa[kk][1], pa[kk][2], pa[kk][3], b2, b3);
            }
        }
    }

    // ---- epilogue: quad-reduce l, write fp16 partials + l ----
    lsum0 += __shfl_xor_sync(0xffffffffu, lsum0, 1);
    lsum0 += __shfl_xor_sync(0xffffffffu, lsum0, 2);
    lsum1 += __shfl_xor_sync(0xffffffffu, lsum1, 1);
    lsum1 += __shfl_xor_sync(0xffffffffu, lsum1, 2);

    const int slot = (b * 32 + qt) * 2 + half;
    __half* po = g_Po + (size_t)slot * (128 * 64);
    #pragma unroll
    for (int n = 0; n < 8; ++n) {
        *(uint32_t*)(po + r0 * 64 + n * 8 + 2 * t4)       = h2pack(o[n][0], o[n][1]);
        *(uint32_t*)(po + (r0 + 8) * 64 + n * 8 + 2 * t4) = h2pack(o[n][2], o[n][3]);
    }
    if (t4 == 0) {
        g_Pl[slot * 128 + r0]     = lsum0;
        g_Pl[slot * 128 + r0 + 8] = lsum1;
    }
}

// ---------------------------------------------------------------------------
// Combine: out = (O0 + O1) / (l0 + l1)   (Po fp16, 8 floats/thread)
// ---------------------------------------------------------------------------
__global__ __launch_bounds__(256) void combine_kernel(float* __restrict__ out)
{
    int i8 = blockIdx.x * 256 + threadIdx.x;     // 262144 octets
    int e  = i8 << 3;
    int r    = (e >> 6) & 127;
    int slot = (e >> 13) << 1;
    const __half* p0 = g_Po + ((size_t)slot * 128 + r) * 64 + (e & 63);
    const __half* p1 = p0 + 128 * 64;
    uint4 ua = *(const uint4*)p0;
    uint4 uc = *(const uint4*)p1;
    float inv = 1.0f / (g_Pl[slot * 128 + r] + g_Pl[(slot + 1) * 128 + r]);

    float2 a0 = __half22float2(*(__half2*)&ua.x);
    float2 a1 = __half22float2(*(__half2*)&ua.y);
    float2 a2 = __half22float2(*(__half2*)&ua.z);
    float2 a3 = __half22float2(*(__half2*)&ua.w);
    float2 c0 = __half22float2(*(__half2*)&uc.x);
    float2 c1 = __half22float2(*(__half2*)&uc.y);
    float2 c2 = __half22float2(*(__half2*)&uc.z);
    float2 c3 = __half22float2(*(__half2*)&uc.w);
    *(float4*)&out[e]     = make_float4((a0.x + c0.x) * inv, (a0.y + c0.y) * inv,
                                        (a1.x + c1.x) * inv, (a1.y + c1.y) * inv);
    *(float4*)&out[e + 4] = make_float4((a2.x + c2.x) * inv, (a2.y + c2.y) * inv,
                                        (a3.x + c3.x) * inv, (a3.y + c3.y) * inv);
}

// ---------------------------------------------------------------------------

extern "C" void kernel_launch(void* const* d_in, const int* in_sizes, int n_in,
                              void* d_out, int out_size)
{
    (void)in_sizes; (void)n_in; (void)out_size;
    const float* x  = (const float*)d_in[0];
    const float* Wk = (const float*)d_in[1];
    const float* Wq = (const float*)d_in[2];
    const float* Wv = (const float*)d_in[3];
    float* out = (float*)d_out;

    cudaFuncSetAttribute(proj_mma_kernel, cudaFuncAttributeMaxDynamicSharedMemorySize,
                         SMEM_PROJ);
    cudaFuncSetAttribute(attn_kernel, cudaFuncAttributeMaxDynamicSharedMemorySize,
                         SMEM_ATTN);

    split_w_kernel<<<18, 256>>>(Wk, Wq, Wv);
    proj_mma_kernel<<<(B_ * T_) / 64, 256, SMEM_PROJ>>>(x);
    attn_kernel<<<dim3(B_, 64), 256, SMEM_ATTN>>>();
    combine_kernel<<<1024, 256>>>(out);
}